// round 2
// baseline (speedup 1.0000x reference)
#include <cuda_runtime.h>
#include <math.h>

#define Bz 256
#define Tt 25
#define Ee 353
#define Hh 191
#define Zz 13
#define Vv 8185
#define G4 764      // 4*H
#define KT 544      // E + H
#define START_TOK 19

// Persistent scratch (no allocations allowed)
__device__ float g_hA[Bz * Hh];
__device__ float g_hB[Bz * Hh];
__device__ float g_c[Bz * Hh];
__device__ int   g_tok[Bz];

__global__ void init_kernel() {
    int i = blockIdx.x * blockDim.x + threadIdx.x;
    if (i < Bz * Hh) { g_hA[i] = 0.f; g_c[i] = 0.f; }
}

__device__ __forceinline__ float sigf(float x) { return 1.f / (1.f + expf(-x)); }

// Fused LSTM step: gathers x = emb[token], computes gates = x@Wk + h@Wr + b,
// applies activations, updates c in place (each (b,h) owned by one thread),
// writes h_new to the other buffer.
// Block tile: 16 batch rows x 16 h-units x 4 gates. Grid (12, 16).
__global__ void lstm_step_kernel(const int* __restrict__ tok, int tok_stride, int tok_off,
                                 const float* __restrict__ emb,
                                 const float* __restrict__ Wk,   // [E,4H]
                                 const float* __restrict__ Wr,   // [H,4H]
                                 const float* __restrict__ bias, // [4H]
                                 const float* __restrict__ h_prev,
                                 float* __restrict__ h_new)
{
    __shared__ float x_s[16][KT + 1];   // +1 pad: avoid 2-way bank conflict (544 % 32 == 0)
    __shared__ float w_s[32][65];       // 32-k chunk x 64 gate-cols, padded
    __shared__ int tok_s[16];

    int tid = threadIdx.x;
    int c = tid & 15;       // h-unit within tile
    int r = tid >> 4;       // batch row within tile
    int c0 = blockIdx.x * 16;
    int r0 = blockIdx.y * 16;

    if (tid < 16) tok_s[tid] = tok[(r0 + tid) * tok_stride + tok_off];
    __syncthreads();

    // Stage the fused input vector [emb[tok] ; h_prev] for 16 rows
    for (int idx = tid; idx < 16 * KT; idx += 256) {
        int rr = idx / KT;
        int k  = idx - rr * KT;
        float v;
        if (k < Ee) v = emb[tok_s[rr] * Ee + k];
        else        v = h_prev[(r0 + rr) * Hh + (k - Ee)];
        x_s[rr][k] = v;
    }

    float a0 = 0.f, a1 = 0.f, a2 = 0.f, a3 = 0.f;
    int cg = c0 + c;
    __syncthreads();

    for (int kc = 0; kc < KT; kc += 32) {
        // Stage 32 x 64 weight tile (4 gate column groups of 16)
        #pragma unroll
        for (int i = 0; i < 8; i++) {
            int idx = tid + i * 256;
            int kk = idx >> 6;
            int gc = idx & 63;
            int gg = gc >> 4;
            int cc = gc & 15;
            float w = 0.f;
            if (c0 + cc < Hh) {
                int col = gg * Hh + c0 + cc;
                int k = kc + kk;
                w = (k < Ee) ? Wk[k * G4 + col] : Wr[(k - Ee) * G4 + col];
            }
            w_s[kk][gc] = w;
        }
        __syncthreads();
        #pragma unroll
        for (int kk = 0; kk < 32; kk++) {
            float xv = x_s[r][kc + kk];
            a0 = fmaf(xv, w_s[kk][c],      a0);
            a1 = fmaf(xv, w_s[kk][16 + c], a1);
            a2 = fmaf(xv, w_s[kk][32 + c], a2);
            a3 = fmaf(xv, w_s[kk][48 + c], a3);
        }
        __syncthreads();
    }

    if (cg < Hh) {
        int rg = r0 + r;
        float iv = sigf(a0 + bias[cg]);
        float fv = sigf(a1 + bias[Hh + cg]);
        float gv = tanhf(a2 + bias[2 * Hh + cg]);
        float ov = sigf(a3 + bias[3 * Hh + cg]);
        float cprev = g_c[rg * Hh + cg];
        float cn = fv * cprev + iv * gv;
        g_c[rg * Hh + cg] = cn;
        h_new[rg * Hh + cg] = ov * tanhf(cn);
    }
}

// Latent head: mu/sigma projection, reparameterize, init decoder state, reset token.
__global__ void latent_kernel(const float* __restrict__ h_enc,
                              const float* __restrict__ eps,
                              const float* __restrict__ mu_w, const float* __restrict__ mu_b,
                              const float* __restrict__ sig_w, const float* __restrict__ sig_b,
                              const float* __restrict__ init_w, const float* __restrict__ init_b,
                              float* __restrict__ h_dec)
{
    __shared__ float hrow[Hh];
    __shared__ float z_s[Zz];
    int b = blockIdx.x, tid = threadIdx.x;
    if (tid < Hh) hrow[tid] = h_enc[b * Hh + tid];
    __syncthreads();
    if (tid < Zz) {
        float mu = mu_b[tid], sg = sig_b[tid];
        for (int k = 0; k < Hh; k++) {
            mu = fmaf(hrow[k], mu_w[k * Zz + tid], mu);
            sg = fmaf(hrow[k], sig_w[k * Zz + tid], sg);
        }
        z_s[tid] = mu + eps[tid] * sg;
    }
    __syncthreads();
    if (tid < Hh) {
        float v = init_b[tid];
        #pragma unroll
        for (int z = 0; z < Zz; z++) v = fmaf(z_s[z], init_w[z * Hh + tid], v);
        h_dec[b * Hh + tid] = v;
        g_c[b * Hh + tid]   = v;
    }
    if (tid == 0) g_tok[b] = START_TOK;
}

// Logits GEMM: out[b, t, v] = h[b]·out_w[:,v] + out_b[v].
// Block tile: 32 rows x 64 v-cols. Grid (128, 8). Thread: 2 v x 4 rows.
__global__ void logits_kernel(const float* __restrict__ h,
                              const float* __restrict__ W,   // [H, V]
                              const float* __restrict__ bo,  // [V]
                              float* __restrict__ out, int t)
{
    __shared__ float h_s[32][Hh];
    int tid = threadIdx.x;
    int v0 = blockIdx.x * 64;
    int r0 = blockIdx.y * 32;

    for (int idx = tid; idx < 32 * Hh; idx += 256) {
        int rr = idx / Hh;
        int k  = idx - rr * Hh;
        h_s[rr][k] = h[(r0 + rr) * Hh + k];
    }
    __syncthreads();

    int va = v0 + (tid & 31);
    int vb = va + 32;
    int ry = tid >> 5;
    int vac = va < Vv ? va : Vv - 1;
    int vbc = vb < Vv ? vb : Vv - 1;

    float acc[4][2] = {};
    #pragma unroll 4
    for (int k = 0; k < Hh; k++) {
        float w0 = W[k * Vv + vac];
        float w1 = W[k * Vv + vbc];
        #pragma unroll
        for (int j = 0; j < 4; j++) {
            float hv = h_s[ry + 8 * j][k];
            acc[j][0] = fmaf(hv, w0, acc[j][0]);
            acc[j][1] = fmaf(hv, w1, acc[j][1]);
        }
    }
    float ba = bo[vac], bb = bo[vbc];
    #pragma unroll
    for (int j = 0; j < 4; j++) {
        int rg = r0 + ry + 8 * j;
        float* orow = out + (size_t)rg * (Tt * Vv) + (size_t)t * Vv;
        if (va < Vv) orow[va] = acc[j][0] + ba;
        if (vb < Vv) orow[vb] = acc[j][1] + bb;
    }
}

// Argmax over V per batch row (first-index tie break, matching jnp.argmax).
__global__ void argmax_kernel(const float* __restrict__ out, int t)
{
    __shared__ float sv[256];
    __shared__ int   si[256];
    int b = blockIdx.x, tid = threadIdx.x;
    const float* row = out + (size_t)b * (Tt * Vv) + (size_t)t * Vv;
    float best = -3.4e38f;
    int bi = 0;
    for (int v = tid; v < Vv; v += 256) {
        float x = row[v];
        if (x > best) { best = x; bi = v; }
    }
    sv[tid] = best; si[tid] = bi;
    __syncthreads();
    for (int s = 128; s > 0; s >>= 1) {
        if (tid < s) {
            if (sv[tid + s] > sv[tid] ||
                (sv[tid + s] == sv[tid] && si[tid + s] < si[tid])) {
                sv[tid] = sv[tid + s];
                si[tid] = si[tid + s];
            }
        }
        __syncthreads();
    }
    if (tid == 0) g_tok[b] = si[0];
}

extern "C" void kernel_launch(void* const* d_in, const int* in_sizes, int n_in,
                              void* d_out, int out_size)
{
    const int*   inputs = (const int*)  d_in[0];
    const float* eps    = (const float*)d_in[1];
    const float* emb    = (const float*)d_in[2];
    const float* inf_k  = (const float*)d_in[3];
    const float* inf_rk = (const float*)d_in[4];
    const float* inf_b  = (const float*)d_in[5];
    const float* mu_w   = (const float*)d_in[6];
    const float* mu_b   = (const float*)d_in[7];
    const float* sig_w  = (const float*)d_in[8];
    const float* sig_b  = (const float*)d_in[9];
    const float* init_w = (const float*)d_in[10];
    const float* init_b = (const float*)d_in[11];
    const float* gen_k  = (const float*)d_in[12];
    const float* gen_rk = (const float*)d_in[13];
    const float* gen_b  = (const float*)d_in[14];
    const float* out_w  = (const float*)d_in[15];
    const float* out_b  = (const float*)d_in[16];
    float* out = (float*)d_out;

    float *hA, *hB;
    int* tokp;
    cudaGetSymbolAddress((void**)&hA,   g_hA);
    cudaGetSymbolAddress((void**)&hB,   g_hB);
    cudaGetSymbolAddress((void**)&tokp, g_tok);

    init_kernel<<<(Bz * Hh + 255) / 256, 256>>>();

    dim3 lgrid(12, 16);   // 12 col tiles (192 >= 191) x 16 row tiles
    dim3 ogrid(128, 8);   // 128 v tiles x 8 row tiles

    // ----- encoder -----
    float* src = hA;
    float* dst = hB;
    for (int t = 0; t < Tt; t++) {
        lstm_step_kernel<<<lgrid, 256>>>(inputs, Tt, t, emb, inf_k, inf_rk, inf_b, src, dst);
        float* tmp = src; src = dst; dst = tmp;
    }

    // ----- latent -----
    latent_kernel<<<Bz, 192>>>(src, eps, mu_w, mu_b, sig_w, sig_b, init_w, init_b, dst);
    { float* tmp = src; src = dst; dst = tmp; }   // src now holds decoder h0 (=c0)

    // ----- autoregressive decoder -----
    for (int t = 0; t < Tt; t++) {
        lstm_step_kernel<<<lgrid, 256>>>(tokp, 1, 0, emb, gen_k, gen_rk, gen_b, src, dst);
        float* tmp = src; src = dst; dst = tmp;
        logits_kernel<<<ogrid, 256>>>(src, out_w, out_b, out, t);
        argmax_kernel<<<Bz, 256>>>(out, t);
    }
}

// round 3
// speedup vs baseline: 1.9871x; 1.9871x over previous
#include <cuda_runtime.h>
#include <math.h>

#define Bz 256
#define Tt 25
#define Ee 353
#define Hh 191
#define Zz 13
#define Vv 8185
#define G4 764      // 4*H
#define NP 768      // padded 4H (gate-interleaved)
#define VP 8192     // padded V
#define START_TOK 19

// -------- persistent device scratch (no allocations allowed) --------
__device__ float g_h[2][Bz * Hh];
__device__ float g_c[Bz * Hh];
__device__ unsigned long long g_amax[2][Bz];
__device__ float g_encx[Bz * Tt * G4];   // encoder input projections (+bias), PG layout
__device__ float g_decp[Vv * G4];        // vocab decoder projections (+bias), PG layout
__device__ float g_wk1[Ee * NP];         // inf_k, PG, padded
__device__ float g_wk2[Ee * NP];         // gen_k, PG, padded
__device__ float g_wr1[Hh * NP];         // inf_rk, PG, padded
__device__ float g_wr2[Hh * NP];         // gen_rk, PG, padded
__device__ float g_wlog[Hh * VP];        // out_w, padded to 8192 cols

// -------- helpers --------
__device__ __forceinline__ float sigf(float x) { return 1.f / (1.f + expf(-x)); }

__device__ __forceinline__ void ffma2(unsigned long long& d, unsigned long long a,
                                      unsigned long long b) {
    asm("fma.rn.f32x2 %0, %1, %2, %3;" : "=l"(d) : "l"(a), "l"(b), "l"(d));
}
__device__ __forceinline__ unsigned long long dup2(float x) {
    unsigned long long r;
    asm("mov.b64 %0, {%1, %1};" : "=l"(r) : "f"(x));
    return r;
}
__device__ __forceinline__ float2 unpk(unsigned long long v) {
    float2 r;
    asm("mov.b64 {%0, %1}, %2;" : "=f"(r.x), "=f"(r.y) : "l"(v));
    return r;
}

// -------- init --------
__global__ void init_kernel() {
    int i = blockIdx.x * blockDim.x + threadIdx.x;
    if (i < Bz * Hh) { g_h[0][i] = 0.f; g_c[i] = 0.f; }
}

// -------- weight permutes --------
// PG layout: out[k][4*j+g] = in[k][g*Hh+j], cols padded to NP with zeros.
__global__ void permute_pg(const float* __restrict__ w, float* __restrict__ o, int K) {
    int i = blockIdx.x * 256 + threadIdx.x;
    if (i >= K * NP) return;
    int k = i / NP, n = i - k * NP;
    float v = 0.f;
    if (n < G4) { int j = n >> 2, g = n & 3; v = w[k * G4 + g * Hh + j]; }
    o[i] = v;
}
// out_w padded to 8192 cols
__global__ void permute_wlog(const float* __restrict__ w, float* __restrict__ o) {
    int i = blockIdx.x * 256 + threadIdx.x;
    if (i >= Hh * VP) return;
    int k = i >> 13, v = i & (VP - 1);
    o[i] = (v < Vv) ? w[k * Vv + v] : 0.f;
}

// -------- input projection GEMM (gathered rows) --------
// outp[m][n] = emb[tok(m)][:] @ Wpg[:, n] + bias_pg(n),  n in PG layout.
// tile 32 rows x 256 cols; thread: 4 rows x 8 cols (f32x2 packed).
__global__ __launch_bounds__(256) void proj_kernel(
    const int* __restrict__ idx, int M,
    const float* __restrict__ emb,
    const float* __restrict__ Wpg,    // [Ee][NP]
    const float* __restrict__ bias,   // [G4] original gate-block order
    float* __restrict__ outp)         // [M][G4]
{
    __shared__ float A[32][Ee + 3];
    int tid = threadIdx.x, cc = tid & 31, rr = tid >> 5;
    int c0 = blockIdx.x * 256, r0 = blockIdx.y * 32;

    for (int i = tid; i < 32 * Ee; i += 256) {
        int r = i / Ee, k = i - r * Ee;
        int m = r0 + r;
        int tok = (m < M) ? (idx ? idx[m] : m) : 0;
        A[r][k] = emb[tok * Ee + k];
    }
    __syncthreads();

    int ca = c0 + cc * 4, cb = ca + 128;
    unsigned long long acc[4][4];
#pragma unroll
    for (int r = 0; r < 4; r++)
#pragma unroll
        for (int q = 0; q < 4; q++) acc[r][q] = 0ull;

    const ulonglong2* wa = (const ulonglong2*)(Wpg + ca);
    const ulonglong2* wb = (const ulonglong2*)(Wpg + cb);
#pragma unroll 2
    for (int k = 0; k < Ee; k++) {
        ulonglong2 w0 = wa[k * (NP / 4)];
        ulonglong2 w1 = wb[k * (NP / 4)];
#pragma unroll
        for (int r = 0; r < 4; r++) {
            unsigned long long hp = dup2(A[rr + 8 * r][k]);
            ffma2(acc[r][0], hp, w0.x);
            ffma2(acc[r][1], hp, w0.y);
            ffma2(acc[r][2], hp, w1.x);
            ffma2(acc[r][3], hp, w1.y);
        }
    }

    int ja = ca >> 2, jb = cb >> 2;
    bool cbok = (jb < Hh);
    float ba[4], bb[4];
#pragma unroll
    for (int g = 0; g < 4; g++) {
        ba[g] = bias[g * Hh + ja];
        bb[g] = cbok ? bias[g * Hh + jb] : 0.f;
    }
#pragma unroll
    for (int r = 0; r < 4; r++) {
        int m = r0 + rr + 8 * r;
        if (m >= M) continue;
        float* op = outp + (size_t)m * G4;
        float2 v01 = unpk(acc[r][0]), v23 = unpk(acc[r][1]);
        float2 v45 = unpk(acc[r][2]), v67 = unpk(acc[r][3]);
        float4 va = make_float4(v01.x + ba[0], v01.y + ba[1], v23.x + ba[2], v23.y + ba[3]);
        *(float4*)(op + ca) = va;
        if (cbok) {
            float4 vb = make_float4(v45.x + bb[0], v45.y + bb[1], v67.x + bb[2], v67.y + bb[3]);
            *(float4*)(op + cb) = vb;
        }
    }
}

// -------- LSTM recurrent step --------
// gates[row][4j+g] = pre[row or tok][4j+g] + h_prev[row]@WrPG[:,4j+g]; then acts.
// mode 0: enc (pre row = row*Tt+t); 1: dec first (START); 2: dec (token from amax_in).
// block 256 = 64 unit-threads x 4 rowthreads; thread: 1 unit, 2 rows. grid (3, 32).
__global__ __launch_bounds__(256) void lstm_step(
    const float* __restrict__ Wpg,      // [Hh][NP]
    const float* __restrict__ h_prev,
    float* __restrict__ h_new,
    const float* __restrict__ pre_base,
    int t, int mode,
    const unsigned long long* __restrict__ amax_in,
    unsigned long long* __restrict__ amax_out)
{
    __shared__ float hs[8][Hh + 1];
    __shared__ float ws[24][260];
    int tid = threadIdx.x;
    int u = tid & 63, rt = tid >> 6;
    int u0 = blockIdx.x * 64, r0 = blockIdx.y * 8;
    int j = u0 + u;
    int row1 = r0 + rt, row2 = row1 + 4;

    if (mode && u == 0 && blockIdx.x == 0) {
        amax_out[row1] = 0ull;
        amax_out[row2] = 0ull;
    }

    for (int i = tid; i < 8 * Hh; i += 256) {
        int r = i / Hh, k = i - r * Hh;
        hs[r][k] = h_prev[(r0 + r) * Hh + k];
    }

    float4 p1 = make_float4(0.f, 0.f, 0.f, 0.f), p2 = p1;
    if (j < Hh) {
        const float *pb1, *pb2;
        if (mode == 0) {
            pb1 = pre_base + ((size_t)row1 * Tt + t) * G4;
            pb2 = pre_base + ((size_t)row2 * Tt + t) * G4;
        } else if (mode == 1) {
            pb1 = pb2 = pre_base + (size_t)START_TOK * G4;
        } else {
            int t1 = Vv - 1 - (int)(unsigned)(amax_in[row1] & 0xFFFFFFFFull);
            int t2 = Vv - 1 - (int)(unsigned)(amax_in[row2] & 0xFFFFFFFFull);
            pb1 = pre_base + (size_t)t1 * G4;
            pb2 = pre_base + (size_t)t2 * G4;
        }
        p1 = *(const float4*)(pb1 + 4 * j);
        p2 = *(const float4*)(pb2 + 4 * j);
    }
    __syncthreads();

    unsigned long long a1[2] = {0ull, 0ull}, a2[2] = {0ull, 0ull};
    for (int kc = 0; kc < Hh; kc += 24) {
        int kn = min(24, Hh - kc);
        for (int i = tid; i < kn * 64; i += 256) {
            int kk = i >> 6, uu = i & 63;
            *(float4*)&ws[kk][uu * 4] = *(const float4*)(Wpg + (kc + kk) * NP + (u0 + uu) * 4);
        }
        __syncthreads();
        for (int kk = 0; kk < kn; kk++) {
            ulonglong2 w = *(const ulonglong2*)&ws[kk][u * 4];
            unsigned long long h1 = dup2(hs[rt][kc + kk]);
            unsigned long long h2 = dup2(hs[rt + 4][kc + kk]);
            ffma2(a1[0], h1, w.x); ffma2(a1[1], h1, w.y);
            ffma2(a2[0], h2, w.x); ffma2(a2[1], h2, w.y);
        }
        __syncthreads();
    }

    if (j < Hh) {
        float2 g01 = unpk(a1[0]), g23 = unpk(a1[1]);
        {
            float iv = sigf(g01.x + p1.x);
            float fv = sigf(g01.y + p1.y);
            float gv = tanhf(g23.x + p1.z);
            float ov = sigf(g23.y + p1.w);
            float cp = g_c[row1 * Hh + j];
            float cn = fv * cp + iv * gv;
            g_c[row1 * Hh + j] = cn;
            h_new[row1 * Hh + j] = ov * tanhf(cn);
        }
        g01 = unpk(a2[0]); g23 = unpk(a2[1]);
        {
            float iv = sigf(g01.x + p2.x);
            float fv = sigf(g01.y + p2.y);
            float gv = tanhf(g23.x + p2.z);
            float ov = sigf(g23.y + p2.w);
            float cp = g_c[row2 * Hh + j];
            float cn = fv * cp + iv * gv;
            g_c[row2 * Hh + j] = cn;
            h_new[row2 * Hh + j] = ov * tanhf(cn);
        }
    }
}

// -------- latent head --------
__global__ void latent_kernel(const float* __restrict__ h_enc, const float* __restrict__ eps,
                              const float* __restrict__ mu_w, const float* __restrict__ mu_b,
                              const float* __restrict__ sig_w, const float* __restrict__ sig_b,
                              const float* __restrict__ init_w, const float* __restrict__ init_b,
                              float* __restrict__ h_dec)
{
    __shared__ float hrow[Hh];
    __shared__ float z_s[Zz];
    int b = blockIdx.x, tid = threadIdx.x;
    if (tid < Hh) hrow[tid] = h_enc[b * Hh + tid];
    __syncthreads();
    if (tid < Zz) {
        float mu = mu_b[tid], sg = sig_b[tid];
        for (int k = 0; k < Hh; k++) {
            mu = fmaf(hrow[k], mu_w[k * Zz + tid], mu);
            sg = fmaf(hrow[k], sig_w[k * Zz + tid], sg);
        }
        z_s[tid] = mu + eps[tid] * sg;
    }
    __syncthreads();
    if (tid < Hh) {
        float v = init_b[tid];
#pragma unroll
        for (int z = 0; z < Zz; z++) v = fmaf(z_s[z], init_w[z * Hh + tid], v);
        h_dec[b * Hh + tid] = v;
        g_c[b * Hh + tid] = v;
    }
}

// -------- logits GEMM + fused argmax --------
// out[row,t,v] = h[row]@Wlog[:,v] + bo[v]; per-row argmax key atomicMax'd into amax.
// tile 32 rows x 256 cols; thread 4 rows x 8 cols (f32x2). grid (32, 8).
__global__ __launch_bounds__(256) void logits_kernel(
    const float* __restrict__ hsrc,
    const float* __restrict__ Wlog,   // [Hh][VP]
    const float* __restrict__ bo,
    float* __restrict__ out, int t,
    unsigned long long* __restrict__ amax)
{
    __shared__ float hs[32][Hh + 1];
    int tid = threadIdx.x, cc = tid & 31, rr = tid >> 5;
    int c0 = blockIdx.x * 256, r0 = blockIdx.y * 32;

    for (int i = tid; i < 32 * Hh; i += 256) {
        int r = i / Hh, k = i - r * Hh;
        hs[r][k] = hsrc[(r0 + r) * Hh + k];
    }
    __syncthreads();

    int ca = c0 + cc * 4, cb = ca + 128;
    unsigned long long acc[4][4];
#pragma unroll
    for (int r = 0; r < 4; r++)
#pragma unroll
        for (int q = 0; q < 4; q++) acc[r][q] = 0ull;

    const ulonglong2* wa = (const ulonglong2*)(Wlog + ca);
    const ulonglong2* wb = (const ulonglong2*)(Wlog + cb);
#pragma unroll 2
    for (int k = 0; k < Hh; k++) {
        ulonglong2 w0 = wa[k * (VP / 4)];
        ulonglong2 w1 = wb[k * (VP / 4)];
#pragma unroll
        for (int r = 0; r < 4; r++) {
            unsigned long long hp = dup2(hs[rr + 8 * r][k]);
            ffma2(acc[r][0], hp, w0.x);
            ffma2(acc[r][1], hp, w0.y);
            ffma2(acc[r][2], hp, w1.x);
            ffma2(acc[r][3], hp, w1.y);
        }
    }

    float ba0 = bo[ca], ba1 = bo[ca + 1], ba2 = bo[ca + 2], ba3 = bo[ca + 3];
    float bb0 = (cb < Vv) ? bo[cb] : 0.f;
    float bb1 = (cb + 1 < Vv) ? bo[cb + 1] : 0.f;
    float bb2 = (cb + 2 < Vv) ? bo[cb + 2] : 0.f;
    float bb3 = (cb + 3 < Vv) ? bo[cb + 3] : 0.f;

#pragma unroll
    for (int r = 0; r < 4; r++) {
        int row = r0 + rr + 8 * r;
        float* orow = out + ((size_t)row * Tt + t) * Vv;
        float2 v01 = unpk(acc[r][0]), v23 = unpk(acc[r][1]);
        float2 v45 = unpk(acc[r][2]), v67 = unpk(acc[r][3]);
        float v[8];
        v[0] = v01.x + ba0; v[1] = v01.y + ba1; v[2] = v23.x + ba2; v[3] = v23.y + ba3;
        v[4] = v45.x + bb0; v[5] = v45.y + bb1; v[6] = v67.x + bb2; v[7] = v67.y + bb3;

        orow[ca] = v[0]; orow[ca + 1] = v[1]; orow[ca + 2] = v[2]; orow[ca + 3] = v[3];
        if (cb < Vv)     orow[cb]     = v[4];
        if (cb + 1 < Vv) orow[cb + 1] = v[5];
        if (cb + 2 < Vv) orow[cb + 2] = v[6];
        if (cb + 3 < Vv) orow[cb + 3] = v[7];

        unsigned long long key = 0ull;
#pragma unroll
        for (int g = 0; g < 8; g++) {
            int col = (g < 4) ? ca + g : cb + g - 4;
            unsigned long long kk2 = 0ull;
            if (col < Vv) {
                unsigned u_ = __float_as_uint(v[g]);
                unsigned m = (u_ & 0x80000000u) ? ~u_ : (u_ | 0x80000000u);
                kk2 = ((unsigned long long)m << 32) | (unsigned)(Vv - 1 - col);
            }
            key = (kk2 > key) ? kk2 : key;
        }
#pragma unroll
        for (int s = 16; s > 0; s >>= 1) {
            unsigned long long o = __shfl_xor_sync(0xFFFFFFFFu, key, s);
            key = (o > key) ? o : key;
        }
        if (cc == 0) atomicMax(&amax[row], key);
    }
}

// -------- host orchestration --------
extern "C" void kernel_launch(void* const* d_in, const int* in_sizes, int n_in,
                              void* d_out, int out_size)
{
    const int*   inputs = (const int*)  d_in[0];
    const float* eps    = (const float*)d_in[1];
    const float* emb    = (const float*)d_in[2];
    const float* inf_k  = (const float*)d_in[3];
    const float* inf_rk = (const float*)d_in[4];
    const float* inf_b  = (const float*)d_in[5];
    const float* mu_w   = (const float*)d_in[6];
    const float* mu_b   = (const float*)d_in[7];
    const float* sig_w  = (const float*)d_in[8];
    const float* sig_b  = (const float*)d_in[9];
    const float* init_w = (const float*)d_in[10];
    const float* init_b = (const float*)d_in[11];
    const float* gen_k  = (const float*)d_in[12];
    const float* gen_rk = (const float*)d_in[13];
    const float* gen_b  = (const float*)d_in[14];
    const float* out_w  = (const float*)d_in[15];
    const float* out_b  = (const float*)d_in[16];
    float* out = (float*)d_out;

    float *hbase, *encx, *decp, *wk1, *wk2, *wr1, *wr2, *wlog;
    unsigned long long* ambase;
    cudaGetSymbolAddress((void**)&hbase,  g_h);
    cudaGetSymbolAddress((void**)&encx,   g_encx);
    cudaGetSymbolAddress((void**)&decp,   g_decp);
    cudaGetSymbolAddress((void**)&wk1,    g_wk1);
    cudaGetSymbolAddress((void**)&wk2,    g_wk2);
    cudaGetSymbolAddress((void**)&wr1,    g_wr1);
    cudaGetSymbolAddress((void**)&wr2,    g_wr2);
    cudaGetSymbolAddress((void**)&wlog,   g_wlog);
    cudaGetSymbolAddress((void**)&ambase, g_amax);

    float* hbuf[2] = {hbase, hbase + Bz * Hh};
    unsigned long long* am[2] = {ambase, ambase + Bz};

    init_kernel<<<(Bz * Hh + 255) / 256, 256>>>();
    permute_pg<<<(Ee * NP + 255) / 256, 256>>>(inf_k, wk1, Ee);
    permute_pg<<<(Ee * NP + 255) / 256, 256>>>(gen_k, wk2, Ee);
    permute_pg<<<(Hh * NP + 255) / 256, 256>>>(inf_rk, wr1, Hh);
    permute_pg<<<(Hh * NP + 255) / 256, 256>>>(gen_rk, wr2, Hh);
    permute_wlog<<<(Hh * VP + 255) / 256, 256>>>(out_w, wlog);

    proj_kernel<<<dim3(3, (Bz * Tt + 31) / 32), 256>>>(inputs, Bz * Tt, emb, wk1, inf_b, encx);
    proj_kernel<<<dim3(3, (Vv + 31) / 32), 256>>>(nullptr, Vv, emb, wk2, gen_b, decp);

    // ----- encoder -----
    int cur = 0;
    for (int t = 0; t < Tt; t++) {
        lstm_step<<<dim3(3, 32), 256>>>(wr1, hbuf[cur], hbuf[cur ^ 1], encx, t, 0,
                                        nullptr, nullptr);
        cur ^= 1;
    }

    // ----- latent -----
    latent_kernel<<<Bz, 192>>>(hbuf[cur], eps, mu_w, mu_b, sig_w, sig_b,
                               init_w, init_b, hbuf[cur ^ 1]);
    cur ^= 1;

    // ----- autoregressive decoder -----
    for (int t = 0; t < Tt; t++) {
        int p = t & 1;
        lstm_step<<<dim3(3, 32), 256>>>(wr2, hbuf[cur], hbuf[cur ^ 1], decp, t,
                                        (t == 0) ? 1 : 2, am[p ^ 1], am[p]);
        cur ^= 1;
        logits_kernel<<<dim3(32, 8), 256>>>(hbuf[cur], wlog, out_b, out, t, am[p]);
    }
}